// round 10
// baseline (speedup 1.0000x reference)
#include <cuda_runtime.h>
#include <cuda_fp16.h>
#include <math.h>

#define BATCH 128
#define NCAP  4608
#define JDIM  8
#define CDIM  10
#define LDIM  16
#define CL    160             // CDIM*LDIM
#define NSPLIT 72             // n-range splits in pass_ro
#define NRANGE (NCAP/NSPLIT)  // 64
#define PAIRS  (NRANGE/2)     // 32 pairs of n per pass_ro block
#define NBLK0  144            // pass0 blocks
#define NPB0   (NCAP/NBLK0)   // 32 n per pass0 block

typedef unsigned long long ull;

// Scratch (static device globals; no dynamic allocation allowed)
__device__ __align__(16) __half g_Wh[(size_t)NCAP * CL * JDIM];          // [n][cl][8j] fp16
__device__ __align__(32) __half g_u[(size_t)CDIM * NCAP * BATCH * LDIM]; // [c][n][b][l] 188.7 MB
__device__ __align__(16) float g_s0[BATCH * CDIM * LDIM];
__device__ __align__(16) float g_s1[BATCH * CDIM * LDIM];
__device__ __align__(16) float g_s2[BATCH * CDIM * LDIM];

// ---- f32x2 packed-math helpers ---------------------------------------------
__device__ __forceinline__ ull pk2(float a, float b) {
    ull r; asm("mov.b64 %0,{%1,%2};" : "=l"(r) : "f"(a), "f"(b)); return r;
}
__device__ __forceinline__ ull fma2(ull a, ull b, ull c) {
    ull d; asm("fma.rn.f32x2 %0,%1,%2,%3;" : "=l"(d) : "l"(a), "l"(b), "l"(c)); return d;
}
__device__ __forceinline__ float lo2(ull a) {
    float f; asm("{ .reg .b32 h; mov.b64 {%0,h}, %1; }" : "=f"(f) : "l"(a)); return f;
}
__device__ __forceinline__ float hi2(ull a) {
    float f; asm("{ .reg .b32 l; mov.b64 {l,%0}, %1; }" : "=f"(f) : "l"(a)); return f;
}
__device__ __forceinline__ ull h2f2(unsigned int h) {
    __half2 hh = *reinterpret_cast<__half2*>(&h);
    float2 f = __half22float2(hh);
    return pk2(f.x, f.y);
}
__device__ __forceinline__ unsigned int cvt2h(float lo, float hi) {
    unsigned int h;
    asm("cvt.rn.f16x2.f32 %0, %1, %2;" : "=r"(h) : "f"(hi), "f"(lo));
    return h;
}
__device__ __forceinline__ float squash_factor(float n2) {
    return n2 / (1.0f + n2) / (sqrtf(n2) + 1e-7f);
}
// Fast exp on fma/alu pipes (no MUFU). |x| <= ~16, rel err ~4e-5.
__device__ __forceinline__ float fexp(float x) {
    float t = x * 1.4426950408889634f;         // x * log2(e)
    float z = t + 12582912.0f;                  // round-to-nearest via magic
    int   ki = __float_as_int(z);               // low bits = (int)round(t)
    float k = z - 12582912.0f;
    float f = t - k;                            // f in [-0.5, 0.5]
    float p = 0.0096181291f;                    // 2^f Taylor (e^(f ln2))
    p = fmaf(p, f, 0.0555041087f);
    p = fmaf(p, f, 0.2402265070f);
    p = fmaf(p, f, 0.6931471806f);
    p = fmaf(p, f, 1.0f);
    return __int_as_float(__float_as_int(p) + (ki << 23));
}
__device__ __forceinline__ void cpasync16(unsigned int sdst, const void* gsrc) {
    asm volatile("cp.async.cg.shared.global [%0], [%1], 16;" :: "r"(sdst), "l"(gsrc) : "memory");
}
__device__ __forceinline__ void cpasync_commit() {
    asm volatile("cp.async.commit_group;" ::: "memory");
}
__device__ __forceinline__ void cpasync_wait1() {
    asm volatile("cp.async.wait_group 1;" ::: "memory");
}
__device__ __forceinline__ void cpasync_wait0() {
    asm volatile("cp.async.wait_group 0;" ::: "memory");
}
__device__ __forceinline__ unsigned int smem_u32(const void* p) {
    return (unsigned int)__cvta_generic_to_shared(p);
}

// ---- HMMA helpers (base ISA: works on plain sm_103 target) ------------------
__device__ __forceinline__ void ldsm_x2(unsigned int& r0, unsigned int& r1, unsigned int a) {
    asm volatile("ldmatrix.sync.aligned.m8n8.x2.shared.b16 {%0,%1}, [%2];"
                 : "=r"(r0), "=r"(r1) : "r"(a));
}
__device__ __forceinline__ void ldsm_x4(unsigned int& r0, unsigned int& r1,
                                        unsigned int& r2, unsigned int& r3, unsigned int a) {
    asm volatile("ldmatrix.sync.aligned.m8n8.x4.shared.b16 {%0,%1,%2,%3}, [%4];"
                 : "=r"(r0), "=r"(r1), "=r"(r2), "=r"(r3) : "r"(a));
}
__device__ __forceinline__ void mma_16n8k8(float* c, unsigned int a0, unsigned int a1,
                                           unsigned int b0) {
    asm volatile("mma.sync.aligned.m16n8k8.row.col.f32.f16.f16.f32 "
                 "{%0,%1,%2,%3}, {%4,%5}, {%6}, {%7,%7,%7,%7};"
                 : "=f"(c[0]), "=f"(c[1]), "=f"(c[2]), "=f"(c[3])
                 : "r"(a0), "r"(a1), "r"(b0), "f"(0.0f));
}

// ---------------------------------------------------------------------------
// W prep: W[n][j][cl] fp32 -> g_Wh[n][cl][8j] fp16 (16B per row); zero s bufs.
// ---------------------------------------------------------------------------
__global__ void transpose_W_kernel(const float* __restrict__ W) {
    int n = blockIdx.x;
    int cl = threadIdx.x;     // 0..159
    if (n < 128) {            // fused zeroing (128*160 = BATCH*CDIM*LDIM)
        int z = n * CL + cl;
        g_s0[z] = 0.0f; g_s1[z] = 0.0f; g_s2[z] = 0.0f;
    }
    const float* Wn = W + (size_t)n * JDIM * CL;
    unsigned int h[4];
#pragma unroll
    for (int p = 0; p < 4; ++p)
        h[p] = cvt2h(Wn[(2 * p) * CL + cl], Wn[(2 * p + 1) * CL + cl]);
    *reinterpret_cast<uint4*>(g_Wh + ((size_t)n * CL + cl) * JDIM) =
        make_uint4(h[0], h[1], h[2], h[3]);
}

// ---------------------------------------------------------------------------
// Pass 0 (HMMA): per n, u[128b x 160cl] = x[128x8] * Wh[160x8]^T via 160
// m16n8k8 tiles. 512 thr (16 warps): warp (w%8) = m-tile, (w/8) = cl half.
// s0 accumulated in fp32 regs, atomically flushed once. u -> fp16 g_u[c][n][b][l].
// ---------------------------------------------------------------------------
__global__ __launch_bounds__(512, 1) void pass0_mma(const float* __restrict__ x) {
    __shared__ __align__(16) __half sA[2][128 * JDIM];   // 4 KB: [b][8j]
    __shared__ __align__(16) __half sB[2][CL * JDIM];    // 5 KB: [cl][8j]

    const int tid  = threadIdx.x;
    const int lane = tid & 31;
    const int wid  = tid >> 5;            // 0..15
    const int w8   = wid & 7;             // m-tile (b rows 16*w8..)
    const int hh   = wid >> 3;            // cl-half (tiles 10*hh..)
    const int n0   = blockIdx.x * NPB0;

    float s0acc[40];
#pragma unroll
    for (int i = 0; i < 40; ++i) s0acc[i] = 0.0f;

    auto fillA = [&](int buf, int n) {
        if (tid < 256) {
            int b = tid >> 1, jh = (tid & 1) * 4;
            const float4 xv = *reinterpret_cast<const float4*>(
                x + ((size_t)b * NCAP + n) * JDIM + jh);
            *reinterpret_cast<uint2*>(&sA[buf][b * JDIM + jh]) =
                make_uint2(cvt2h(xv.x, xv.y), cvt2h(xv.z, xv.w));
        }
    };
    auto fillB = [&](int buf, int n) {
        if (tid >= 256 && tid < 256 + CL) {
            int cl = tid - 256;
            cpasync16(smem_u32(&sB[buf][cl * JDIM]),
                      g_Wh + ((size_t)n * CL + cl) * JDIM);
        }
    };

    fillA(0, n0); fillB(0, n0); cpasync_commit();

    const unsigned int aaddr  = smem_u32(&sA[0][(w8 * 16 + (lane & 15)) * JDIM]);
    const unsigned int baddr0 = smem_u32(&sB[0][(hh * 80 + lane) * JDIM]);
    const unsigned int baddr1 = smem_u32(&sB[0][(hh * 80 + 32 + lane) * JDIM]);
    const unsigned int baddr2 = smem_u32(&sB[0][(hh * 80 + 64 + (lane & 15)) * JDIM]);
    const unsigned int strA = 128 * JDIM * 2;
    const unsigned int strB = CL * JDIM * 2;

    const int brow = w8 * 16 + (lane >> 2);
    const int lodd = (lane & 3) * 2;

    for (int i = 0; i < NPB0; ++i) {
        const int buf = i & 1;
        const int n = n0 + i;
        cpasync_wait0();
        __syncthreads();
        if (i + 1 < NPB0) { fillA(buf ^ 1, n + 1); fillB(buf ^ 1, n + 1); }
        cpasync_commit();

        unsigned int a0, a1, bf[10];
        ldsm_x2(a0, a1, aaddr + buf * strA);
        ldsm_x4(bf[0], bf[1], bf[2], bf[3], baddr0 + buf * strB);
        ldsm_x4(bf[4], bf[5], bf[6], bf[7], baddr1 + buf * strB);
        ldsm_x2(bf[8], bf[9], baddr2 + buf * strB);

        const size_t nbase = (size_t)n * BATCH * LDIM + (size_t)brow * LDIM + lodd;
#pragma unroll
        for (int tt = 0; tt < 10; ++tt) {
            float c4[4];
            mma_16n8k8(c4, a0, a1, bf[tt]);
            s0acc[tt * 4 + 0] += c4[0];
            s0acc[tt * 4 + 1] += c4[1];
            s0acc[tt * 4 + 2] += c4[2];
            s0acc[tt * 4 + 3] += c4[3];
            const int g = hh * 10 + tt;
            const int cc = g >> 1;
            const int l8 = (g & 1) * 8;
            const size_t off = (size_t)cc * ((size_t)NCAP * BATCH * LDIM) + nbase + l8;
            *reinterpret_cast<unsigned int*>(g_u + off) = cvt2h(c4[0], c4[1]);
            *reinterpret_cast<unsigned int*>(g_u + off + 8 * LDIM) = cvt2h(c4[2], c4[3]);
        }
    }

#pragma unroll
    for (int tt = 0; tt < 10; ++tt) {
        const int g = hh * 10 + tt;
        const int cc = g >> 1;
        const int l8 = (g & 1) * 8;
        float* d0 = g_s0 + (brow * CDIM + cc) * LDIM + l8 + lodd;
        atomicAdd(d0,     s0acc[tt * 4 + 0]);
        atomicAdd(d0 + 1, s0acc[tt * 4 + 1]);
        float* d1 = g_s0 + ((brow + 8) * CDIM + cc) * LDIM + l8 + lodd;
        atomicAdd(d1,     s0acc[tt * 4 + 2]);
        atomicAdd(d1 + 1, s0acc[tt * 4 + 3]);
    }
}

// ---------------------------------------------------------------------------
// Passes 1 & 2: cp.async-pipelined read of fp16 u; exp on fma/alu pipes.
// ---------------------------------------------------------------------------
template <int MODE>
__global__ __launch_bounds__(320, 2) void pass_ro_kernel(const float* __restrict__ biases) {
    __shared__ __align__(16) __half sU[2][2][CDIM][32][LDIM];  // 40 KB
    __shared__ float sE[CDIM][2][32];

    const int tid  = threadIdx.x;
    const int lane = tid & 31;              // local b
    const int c    = tid >> 5;              // 0..9
    const int b    = blockIdx.x * 32 + lane;
    const int Bb   = blockIdx.x * 32;
    const int nbeg = blockIdx.y * NRANGE;

    ull v2[8];
    {
        float v[LDIM];
        float n20 = 0.0f;
#pragma unroll
        for (int l = 0; l < LDIM; ++l) {
            float s = 0.1f * g_s0[(b * CDIM + c) * LDIM + l] + biases[c * LDIM + l];
            v[l] = s; n20 += s * s;
        }
        float f0 = squash_factor(n20);
        if (MODE == 1) {
#pragma unroll
            for (int p = 0; p < 8; ++p) v2[p] = pk2(f0 * v[2 * p], f0 * v[2 * p + 1]);
        } else {
            float w[LDIM];
            float n21 = 0.0f;
#pragma unroll
            for (int l = 0; l < LDIM; ++l) {
                float s = g_s1[(b * CDIM + c) * LDIM + l] + biases[c * LDIM + l];
                w[l] = s; n21 += s * s;
            }
            float f1 = squash_factor(n21);
#pragma unroll
            for (int p = 0; p < 8; ++p)
                v2[p] = pk2(f0 * v[2 * p] + f1 * w[2 * p],
                            f0 * v[2 * p + 1] + f1 * w[2 * p + 1]);
        }
    }

    const unsigned int su_base = smem_u32(&sU[0][0][0][0][0]);

    auto fill = [&](int s, int p) {
        const int n0 = nbeg + p * 2;
#pragma unroll
        for (int q = 0; q < 4; ++q) {
            int k    = tid + q * 320;
            int i    = (k >= 640) ? 1 : 0;
            int r    = k - i * 640;
            int cp   = r >> 6;
            int rem  = r & 63;
            int bp   = rem >> 1;
            int half = (rem & 1) << 3;
            const __half* gsrc = g_u +
                (((size_t)cp * NCAP + (n0 + i)) * BATCH + (Bb + bp)) * LDIM + half;
            unsigned int sdst = su_base +
                ((((s * 2 + i) * CDIM + cp) * 32 + bp) * LDIM + half) * 2;
            cpasync16(sdst, gsrc);
        }
    };

    ull sacc2[8];
#pragma unroll
    for (int p = 0; p < 8; ++p) sacc2[p] = 0ull;

    fill(0, 0); cpasync_commit();
    fill(1, 1); cpasync_commit();

    for (int it = 0; it < PAIRS; ++it) {
        const int st = it & 1;
        cpasync_wait1();
        __syncthreads();

        const uint4* pa = reinterpret_cast<const uint4*>(&sU[st][0][c][lane][0]);
        uint4 a0 = pa[0], a1 = pa[1];
        const uint4* pb = reinterpret_cast<const uint4*>(&sU[st][1][c][lane][0]);
        uint4 b0 = pb[0], b1 = pb[1];

        {
            ull bd2 = 0ull;
            bd2 = fma2(h2f2(a0.x), v2[0], bd2);
            bd2 = fma2(h2f2(a0.y), v2[1], bd2);
            bd2 = fma2(h2f2(a0.z), v2[2], bd2);
            bd2 = fma2(h2f2(a0.w), v2[3], bd2);
            bd2 = fma2(h2f2(a1.x), v2[4], bd2);
            bd2 = fma2(h2f2(a1.y), v2[5], bd2);
            bd2 = fma2(h2f2(a1.z), v2[6], bd2);
            bd2 = fma2(h2f2(a1.w), v2[7], bd2);
            sE[c][0][lane] = fexp(lo2(bd2) + hi2(bd2));
        }
        {
            ull bd2 = 0ull;
            bd2 = fma2(h2f2(b0.x), v2[0], bd2);
            bd2 = fma2(h2f2(b0.y), v2[1], bd2);
            bd2 = fma2(h2f2(b0.z), v2[2], bd2);
            bd2 = fma2(h2f2(b0.w), v2[3], bd2);
            bd2 = fma2(h2f2(b1.x), v2[4], bd2);
            bd2 = fma2(h2f2(b1.y), v2[5], bd2);
            bd2 = fma2(h2f2(b1.z), v2[6], bd2);
            bd2 = fma2(h2f2(b1.w), v2[7], bd2);
            sE[c][1][lane] = fexp(lo2(bd2) + hi2(bd2));
        }
        __syncthreads();
        {
            float s0 = 0.0f, s1 = 0.0f;
#pragma unroll
            for (int cc = 0; cc < CDIM; ++cc) {
                s0 += sE[cc][0][lane];
                s1 += sE[cc][1][lane];
            }
            float c0 = __fdividef(sE[c][0][lane], s0);
            float c1 = __fdividef(sE[c][1][lane], s1);
            ull cc0 = pk2(c0, c0), cc1 = pk2(c1, c1);
            sacc2[0] = fma2(h2f2(a0.x), cc0, sacc2[0]);
            sacc2[1] = fma2(h2f2(a0.y), cc0, sacc2[1]);
            sacc2[2] = fma2(h2f2(a0.z), cc0, sacc2[2]);
            sacc2[3] = fma2(h2f2(a0.w), cc0, sacc2[3]);
            sacc2[4] = fma2(h2f2(a1.x), cc0, sacc2[4]);
            sacc2[5] = fma2(h2f2(a1.y), cc0, sacc2[5]);
            sacc2[6] = fma2(h2f2(a1.z), cc0, sacc2[6]);
            sacc2[7] = fma2(h2f2(a1.w), cc0, sacc2[7]);
            sacc2[0] = fma2(h2f2(b0.x), cc1, sacc2[0]);
            sacc2[1] = fma2(h2f2(b0.y), cc1, sacc2[1]);
            sacc2[2] = fma2(h2f2(b0.z), cc1, sacc2[2]);
            sacc2[3] = fma2(h2f2(b0.w), cc1, sacc2[3]);
            sacc2[4] = fma2(h2f2(b1.x), cc1, sacc2[4]);
            sacc2[5] = fma2(h2f2(b1.y), cc1, sacc2[5]);
            sacc2[6] = fma2(h2f2(b1.z), cc1, sacc2[6]);
            sacc2[7] = fma2(h2f2(b1.w), cc1, sacc2[7]);
        }

        if (it + 2 < PAIRS) fill(st, it + 2);
        cpasync_commit();
    }

    float* dst = (MODE == 1 ? g_s1 : g_s2) + (b * CDIM + c) * LDIM;
#pragma unroll
    for (int p = 0; p < 8; ++p) {
        atomicAdd(dst + 2 * p,     lo2(sacc2[p]));
        atomicAdd(dst + 2 * p + 1, hi2(sacc2[p]));
    }
}

__global__ void squash_out_kernel(const float* __restrict__ biases, float* __restrict__ out) {
    int idx = blockIdx.x * blockDim.x + threadIdx.x;   // (b*C + c)
    if (idx >= BATCH * CDIM) return;
    int c = idx % CDIM;
    float s[LDIM];
    float n2 = 0.0f;
#pragma unroll
    for (int l = 0; l < LDIM; ++l) {
        s[l] = g_s2[idx * LDIM + l] + biases[c * LDIM + l];
        n2 += s[l] * s[l];
    }
    float f = squash_factor(n2);
#pragma unroll
    for (int l = 0; l < LDIM; ++l) out[idx * LDIM + l] = f * s[l];
}

extern "C" void kernel_launch(void* const* d_in, const int* in_sizes, int n_in,
                              void* d_out, int out_size) {
    const float* inputs = (const float*)d_in[0];   // [128,4608,8]
    const float* W      = (const float*)d_in[1];   // [4608,8,160]
    const float* biases = (const float*)d_in[2];   // [10,16]
    float* out = (float*)d_out;                    // [128,10,16]

    transpose_W_kernel<<<NCAP, CL>>>(W);           // also zeroes s0/s1/s2
    pass0_mma<<<NBLK0, 512>>>(inputs);
    pass_ro_kernel<1><<<dim3(BATCH / 32, NSPLIT), 320>>>(biases);  // (4,72)
    pass_ro_kernel<2><<<dim3(BATCH / 32, NSPLIT), 320>>>(biases);  // (4,72)
    squash_out_kernel<<<(BATCH * CDIM + 255) / 256, 256>>>(biases, out);
}

// round 12
// speedup vs baseline: 1.2890x; 1.2890x over previous
#include <cuda_runtime.h>
#include <cuda_fp16.h>
#include <math.h>

#define BATCH 128
#define NCAP  4608
#define JDIM  8
#define CDIM  10
#define LDIM  16
#define CL    160
#define BSPL  4               // b-splits (32 b each)
#define NSPL  72              // n-splits
#define FN    (NCAP/NSPL)     // 64 n per block
#define THR   320

// smem byte offsets (dynamic smem)
#define SM_X   0                     // 64n*32b*8j fp16 = 32768
#define SM_W   32768                 // 4 stages * 160*8 fp16 = 10240
#define SM_V   43008                 // 10c*32b*16l fp32 = 20480
#define SM_BD  63488                 // 10*32 fp32 = 1280
#define SM_EX  64768
#define SM_CO  66048
#define SM_TOT 67328

// Scratch (static device globals; no dynamic allocation allowed)
__device__ __align__(16) __half g_Wh[(size_t)NCAP * CL * JDIM];  // [n][cl][8j] fp16
__device__ __align__(16) float g_s0[BATCH * CDIM * LDIM];
__device__ __align__(16) float g_s1[BATCH * CDIM * LDIM];
__device__ __align__(16) float g_s2[BATCH * CDIM * LDIM];

// ---- helpers ----------------------------------------------------------------
__device__ __forceinline__ unsigned int cvt2h(float lo, float hi) {
    unsigned int h;
    asm("cvt.rn.f16x2.f32 %0, %1, %2;" : "=r"(h) : "f"(hi), "f"(lo));
    return h;
}
__device__ __forceinline__ float squash_factor(float n2) {
    return n2 / (1.0f + n2) / (sqrtf(n2) + 1e-7f);
}
// Fast exp on fma/alu pipes. |x| small, rel err ~4e-5.
__device__ __forceinline__ float fexp(float x) {
    float t = x * 1.4426950408889634f;
    float z = t + 12582912.0f;
    int   ki = __float_as_int(z);
    float k = z - 12582912.0f;
    float f = t - k;
    float p = 0.0096181291f;
    p = fmaf(p, f, 0.0555041087f);
    p = fmaf(p, f, 0.2402265070f);
    p = fmaf(p, f, 0.6931471806f);
    p = fmaf(p, f, 1.0f);
    return __int_as_float(__float_as_int(p) + (ki << 23));
}
__device__ __forceinline__ void cpasync16(unsigned int sdst, const void* gsrc) {
    asm volatile("cp.async.cg.shared.global [%0], [%1], 16;" :: "r"(sdst), "l"(gsrc) : "memory");
}
__device__ __forceinline__ void cpasync_commit() {
    asm volatile("cp.async.commit_group;" ::: "memory");
}
__device__ __forceinline__ void cpasync_wait2() {
    asm volatile("cp.async.wait_group 2;" ::: "memory");
}
__device__ __forceinline__ unsigned int smem_u32(const void* p) {
    return (unsigned int)__cvta_generic_to_shared(p);
}
__device__ __forceinline__ void ldsm_x2(unsigned int& r0, unsigned int& r1, unsigned int a) {
    asm volatile("ldmatrix.sync.aligned.m8n8.x2.shared.b16 {%0,%1}, [%2];"
                 : "=r"(r0), "=r"(r1) : "r"(a));
}
__device__ __forceinline__ void ldsm_x4(unsigned int& r0, unsigned int& r1,
                                        unsigned int& r2, unsigned int& r3, unsigned int a) {
    asm volatile("ldmatrix.sync.aligned.m8n8.x4.shared.b16 {%0,%1,%2,%3}, [%4];"
                 : "=r"(r0), "=r"(r1), "=r"(r2), "=r"(r3) : "r"(a));
}
__device__ __forceinline__ void mma_16n8k8(float* c, unsigned int a0, unsigned int a1,
                                           unsigned int b0) {
    asm volatile("mma.sync.aligned.m16n8k8.row.col.f32.f16.f16.f32 "
                 "{%0,%1,%2,%3}, {%4,%5}, {%6}, {%7,%7,%7,%7};"
                 : "=f"(c[0]), "=f"(c[1]), "=f"(c[2]), "=f"(c[3])
                 : "r"(a0), "r"(a1), "r"(b0), "f"(0.0f));
}

// ---------------------------------------------------------------------------
// W prep: W[n][j][cl] fp32 -> g_Wh[n][cl][8j] fp16; zero s buffers.
// ---------------------------------------------------------------------------
__global__ void transpose_W_kernel(const float* __restrict__ W) {
    int n = blockIdx.x;
    int cl = threadIdx.x;     // 0..159
    if (n < 128) {
        int z = n * CL + cl;
        g_s0[z] = 0.0f; g_s1[z] = 0.0f; g_s2[z] = 0.0f;
    }
    const float* Wn = W + (size_t)n * JDIM * CL;
    unsigned int h[4];
#pragma unroll
    for (int p = 0; p < 4; ++p)
        h[p] = cvt2h(Wn[(2 * p) * CL + cl], Wn[(2 * p + 1) * CL + cl]);
    *reinterpret_cast<uint4*>(g_Wh + ((size_t)n * CL + cl) * JDIM) =
        make_uint4(h[0], h[1], h[2], h[3]);
}

// ---------------------------------------------------------------------------
// Fused routing pass: recomputes u via HMMA per n; no u tensor in memory.
// Block: 32 b (blockIdx.x), 64 n (blockIdx.y). 320 thr / 10 warps.
// Warp w: m-tile mt=w&1 (16 b), capsules cA=w>>1, cB=cA+5.
// MODE 0: s0 += u (raw; consumers scale by 1/C).
// MODE 1: v = squash(s0/C+bias);                 s1 += coef*u.
// MODE 2: v = squash(s0/C+bias)+squash(s1+bias); s2 += coef*u.
// ---------------------------------------------------------------------------
template <int MODE>
__global__ __launch_bounds__(THR, 2) void fused_pass(const float* __restrict__ x,
                                                     const float* __restrict__ biases) {
    extern __shared__ __align__(16) char smem[];
    __half* sX = (__half*)(smem + SM_X);
    float*  sV  = (float*)(smem + SM_V);
    float*  sBd = (float*)(smem + SM_BD);
    float*  sEx = (float*)(smem + SM_EX);
    float*  sCo = (float*)(smem + SM_CO);

    const int tid  = threadIdx.x;
    const int lane = tid & 31;
    const int w    = tid >> 5;          // 0..9
    const int mt   = w & 1;
    const int cA   = w >> 1;            // 0..4
    const int cB   = cA + 5;
    const int Bb   = blockIdx.x * 32;
    const int nbeg = blockIdx.y * FN;

    // ---- prologue: stage x chunk (32 KB fp16) ----
    for (int k = tid; k < 32 * FN * 2; k += THR) {
        int b   = k >> 7;               // /128
        int rem = k & 127;
        int nl  = rem >> 1;
        int jh  = (rem & 1) * 4;
        float4 xv = *(const float4*)(x + ((size_t)(Bb + b) * NCAP + nbeg + nl) * JDIM + jh);
        *(uint2*)&sX[(nl * 32 + b) * JDIM + jh] =
            make_uint2(cvt2h(xv.x, xv.y), cvt2h(xv.z, xv.w));
    }
    // ---- prologue: v per (b,c) (flat: thread = (tid&31, tid>>5)) ----
    if (MODE >= 1) {
        int b = tid & 31, c = tid >> 5;
        const float4* s0p = (const float4*)(g_s0 + ((size_t)(Bb + b) * CDIM + c) * LDIM);
        const float4* bp  = (const float4*)(biases + c * LDIM);
        float v[16]; float n20 = 0.0f;
#pragma unroll
        for (int q = 0; q < 4; ++q) {
            float4 sv = s0p[q], bv = bp[q];
            v[q*4+0] = 0.1f*sv.x + bv.x; v[q*4+1] = 0.1f*sv.y + bv.y;
            v[q*4+2] = 0.1f*sv.z + bv.z; v[q*4+3] = 0.1f*sv.w + bv.w;
            n20 += v[q*4+0]*v[q*4+0] + v[q*4+1]*v[q*4+1]
                 + v[q*4+2]*v[q*4+2] + v[q*4+3]*v[q*4+3];
        }
        float f0 = squash_factor(n20);
        if (MODE == 1) {
#pragma unroll
            for (int l = 0; l < 16; ++l) v[l] *= f0;
        } else {
            const float4* s1p = (const float4*)(g_s1 + ((size_t)(Bb + b) * CDIM + c) * LDIM);
            float wv[16]; float n21 = 0.0f;
#pragma unroll
            for (int q = 0; q < 4; ++q) {
                float4 sv = s1p[q], bv = bp[q];
                wv[q*4+0] = sv.x + bv.x; wv[q*4+1] = sv.y + bv.y;
                wv[q*4+2] = sv.z + bv.z; wv[q*4+3] = sv.w + bv.w;
                n21 += wv[q*4+0]*wv[q*4+0] + wv[q*4+1]*wv[q*4+1]
                     + wv[q*4+2]*wv[q*4+2] + wv[q*4+3]*wv[q*4+3];
            }
            float f1 = squash_factor(n21);
#pragma unroll
            for (int l = 0; l < 16; ++l) v[l] = f0 * v[l] + f1 * wv[l];
        }
        float4* dv = (float4*)(sV + (c * 32 + b) * 16);
#pragma unroll
        for (int q = 0; q < 4; ++q)
            dv[q] = make_float4(v[q*4+0], v[q*4+1], v[q*4+2], v[q*4+3]);
    }
    __syncthreads();

    // per-thread v fragments (2 b-rows x 2 c x 2 cols x 2 tiles)
    const int blq  = mt * 16 + (lane >> 2);      // local b of frag row
    const int lodd = (lane & 3) * 2;
    float Vl[4][2], Vh[4][2];
    if (MODE >= 1) {
#pragma unroll
        for (int t = 0; t < 4; ++t) {
            int ct = (t < 2) ? cA : cB;
            int l0 = (t & 1) * 8 + lodd;
            Vl[t][0] = sV[(ct * 32 + blq) * 16 + l0];
            Vl[t][1] = sV[(ct * 32 + blq) * 16 + l0 + 1];
            Vh[t][0] = sV[(ct * 32 + blq + 8) * 16 + l0];
            Vh[t][1] = sV[(ct * 32 + blq + 8) * 16 + l0 + 1];
        }
    }

    // ---- W cp.async ring (4 stages) ----
    const unsigned int swb = smem_u32(smem + SM_W);
    auto fillW = [&](int stage, int i) {
        if (tid < CL && i < FN)
            cpasync16(swb + stage * 2560 + tid * 16,
                      g_Wh + ((size_t)(nbeg + i) * CL + tid) * JDIM);
    };
    fillW(0, 0); cpasync_commit();
    fillW(1, 1); cpasync_commit();
    fillW(2, 2); cpasync_commit();

    // ldmatrix addresses
    const unsigned int aaddr0 = smem_u32(sX) + (mt * 16 + (lane & 15)) * JDIM * 2;
    const int clrow = ((lane < 16) ? cA * 16 + lane : cB * 16 + lane - 16);
    const unsigned int baddr0 = swb + clrow * 16;

    float sacc[4][4];
#pragma unroll
    for (int t = 0; t < 4; ++t)
#pragma unroll
        for (int k = 0; k < 4; ++k) sacc[t][k] = 0.0f;

    for (int i = 0; i < FN; ++i) {
        const int st = i & 3;
        cpasync_wait2();
        __syncthreads();                         // bar A: stage st ready; smem reusable
        fillW((i + 3) & 3, i + 3); cpasync_commit();

        unsigned int a0, a1, bf0, bf1, bf2, bf3;
        ldsm_x2(a0, a1, aaddr0 + i * 512);
        ldsm_x4(bf0, bf1, bf2, bf3, baddr0 + st * 2560);
        float c4[4][4];
        mma_16n8k8(c4[0], a0, a1, bf0);
        mma_16n8k8(c4[1], a0, a1, bf1);
        mma_16n8k8(c4[2], a0, a1, bf2);
        mma_16n8k8(c4[3], a0, a1, bf3);

        if (MODE == 0) {
#pragma unroll
            for (int t = 0; t < 4; ++t)
#pragma unroll
                for (int k = 0; k < 4; ++k) sacc[t][k] += c4[t][k];
        } else {
            // bd = u . v per (b-row, c); quad-reduce
            float bla = c4[0][0]*Vl[0][0] + c4[0][1]*Vl[0][1]
                      + c4[1][0]*Vl[1][0] + c4[1][1]*Vl[1][1];
            float bha = c4[0][2]*Vh[0][0] + c4[0][3]*Vh[0][1]
                      + c4[1][2]*Vh[1][0] + c4[1][3]*Vh[1][1];
            float blb = c4[2][0]*Vl[2][0] + c4[2][1]*Vl[2][1]
                      + c4[3][0]*Vl[3][0] + c4[3][1]*Vl[3][1];
            float bhb = c4[2][2]*Vh[2][0] + c4[2][3]*Vh[2][1]
                      + c4[3][2]*Vh[3][0] + c4[3][3]*Vh[3][1];
#pragma unroll
            for (int d = 1; d <= 2; d <<= 1) {
                bla += __shfl_xor_sync(0xFFFFFFFFu, bla, d);
                bha += __shfl_xor_sync(0xFFFFFFFFu, bha, d);
                blb += __shfl_xor_sync(0xFFFFFFFFu, blb, d);
                bhb += __shfl_xor_sync(0xFFFFFFFFu, bhb, d);
            }
            {   // distributed single STS: lane%4 selects which of the 4 values
                int sel = lane & 3;
                float bv = (sel == 0) ? bla : (sel == 1) ? bha : (sel == 2) ? blb : bhb;
                int bb = mt * 16 + (lane >> 2) + ((sel & 1) ? 8 : 0);
                int cc = (sel & 2) ? cB : cA;
                sBd[cc * 32 + bb] = bv;
            }
            __syncthreads();                     // bar B: sBd ready
            float e_own;
            {
                int b = tid & 31, c = tid >> 5;
                e_own = fexp(sBd[c * 32 + b]);
                sEx[c * 32 + b] = e_own;
            }
            __syncthreads();                     // bar C: sEx ready
            {
                int b = tid & 31, c = tid >> 5;
                float s = 0.0f;
#pragma unroll
                for (int cc = 0; cc < CDIM; ++cc) s += sEx[cc * 32 + b];
                sCo[c * 32 + b] = __fdividef(e_own, s);
            }
            __syncthreads();                     // bar D: sCo ready
            {
                float cla = sCo[cA * 32 + blq];
                float cha = sCo[cA * 32 + blq + 8];
                float clb = sCo[cB * 32 + blq];
                float chb = sCo[cB * 32 + blq + 8];
#pragma unroll
                for (int t = 0; t < 2; ++t) {
                    sacc[t][0] += cla * c4[t][0];
                    sacc[t][1] += cla * c4[t][1];
                    sacc[t][2] += cha * c4[t][2];
                    sacc[t][3] += cha * c4[t][3];
                }
#pragma unroll
                for (int t = 2; t < 4; ++t) {
                    sacc[t][0] += clb * c4[t][0];
                    sacc[t][1] += clb * c4[t][1];
                    sacc[t][2] += chb * c4[t][2];
                    sacc[t][3] += chb * c4[t][3];
                }
            }
        }
    }

    // flush partials
    float* dst = (MODE == 0) ? g_s0 : (MODE == 1) ? g_s1 : g_s2;
    const int bg = Bb + blq;
#pragma unroll
    for (int t = 0; t < 4; ++t) {
        int ct = (t < 2) ? cA : cB;
        int l0 = (t & 1) * 8 + lodd;
        atomicAdd(&dst[((size_t)bg * CDIM + ct) * LDIM + l0],     sacc[t][0]);
        atomicAdd(&dst[((size_t)bg * CDIM + ct) * LDIM + l0 + 1], sacc[t][1]);
        atomicAdd(&dst[((size_t)(bg + 8) * CDIM + ct) * LDIM + l0],     sacc[t][2]);
        atomicAdd(&dst[((size_t)(bg + 8) * CDIM + ct) * LDIM + l0 + 1], sacc[t][3]);
    }
}

__global__ void squash_out_kernel(const float* __restrict__ biases, float* __restrict__ out) {
    int idx = blockIdx.x * blockDim.x + threadIdx.x;   // (b*C + c)
    if (idx >= BATCH * CDIM) return;
    int c = idx % CDIM;
    float s[LDIM];
    float n2 = 0.0f;
#pragma unroll
    for (int l = 0; l < LDIM; ++l) {
        s[l] = g_s2[idx * LDIM + l] + biases[c * LDIM + l];
        n2 += s[l] * s[l];
    }
    float f = squash_factor(n2);
#pragma unroll
    for (int l = 0; l < LDIM; ++l) out[idx * LDIM + l] = f * s[l];
}

extern "C" void kernel_launch(void* const* d_in, const int* in_sizes, int n_in,
                              void* d_out, int out_size) {
    const float* inputs = (const float*)d_in[0];   // [128,4608,8]
    const float* W      = (const float*)d_in[1];   // [4608,8,160]
    const float* biases = (const float*)d_in[2];   // [10,16]
    float* out = (float*)d_out;                    // [128,10,16]

    cudaFuncSetAttribute(fused_pass<0>, cudaFuncAttributeMaxDynamicSharedMemorySize, SM_TOT);
    cudaFuncSetAttribute(fused_pass<1>, cudaFuncAttributeMaxDynamicSharedMemorySize, SM_TOT);
    cudaFuncSetAttribute(fused_pass<2>, cudaFuncAttributeMaxDynamicSharedMemorySize, SM_TOT);

    transpose_W_kernel<<<NCAP, CL>>>(W);           // also zeroes s0/s1/s2
    dim3 grid(BSPL, NSPL);                         // (4, 72) = 288 blocks
    fused_pass<0><<<grid, THR, SM_TOT>>>(inputs, biases);
    fused_pass<1><<<grid, THR, SM_TOT>>>(inputs, biases);
    fused_pass<2><<<grid, THR, SM_TOT>>>(inputs, biases);
    squash_out_kernel<<<(BATCH * CDIM + 255) / 256, 256>>>(biases, out);
}